// round 4
// baseline (speedup 1.0000x reference)
#include <cuda_runtime.h>
#include <math.h>

// ---------------- constants ----------------
#define RES   56
#define WS    7
#define SHIFT 3
#define DIM   192
#define HEADS 6
#define HD    32
#define NTOK  49
#define BATCH 32
#define NWIN  64
#define BW    (BATCH*NWIN)        // 2048 windows
#define TTOK  (BW*NTOK)           // 100352 rows
#define SCALE 0.17677669529663687f

#define W_QKV_OFF  0
#define W_QKV_N    (DIM*3*DIM)          // 110592
#define W_PROJ_OFF (W_QKV_OFF + W_QKV_N)
#define W_PROJ_N   (DIM*DIM)            // 36864
#define W_FC1_OFF  (W_PROJ_OFF + W_PROJ_N)
#define W_FC1_N    (DIM*4*DIM)          // 147456
#define W_FC2_OFF  (W_FC1_OFF + W_FC1_N)
#define W_FC2_N    (4*DIM*DIM)          // 147456
#define W_TOTAL    (W_FC2_OFF + W_FC2_N)

// ---------------- scratch ----------------
__device__ float g_hln[TTOK*DIM];
__device__ float g_q  [TTOK*DIM];
__device__ float g_k  [TTOK*DIM];
__device__ float g_v  [TTOK*DIM];
__device__ float g_ao [TTOK*DIM];
__device__ float g_xn [TTOK*DIM];
__device__ float g_ml [TTOK*4*DIM];
__device__ float g_wr [W_TOTAL];          // tf32-rounded weights

__device__ __forceinline__ unsigned f2tf(float x) {
    unsigned r; asm("cvt.rna.tf32.f32 %0, %1;" : "=r"(r) : "f"(x)); return r;
}
__device__ __forceinline__ float tfround(float x) { return __uint_as_float(f2tf(x)); }

__device__ __forceinline__ int win_src_token(int m) {
    int win = m / NTOK, n = m - win * NTOK;
    int b   = win >> 6, wi = win & 63;
    int wy  = wi >> 3,  wx = wi & 7;
    int py  = n / WS,   px = n - py * WS;
    int y = wy * WS + py + SHIFT; if (y >= RES) y -= RES;
    int x = wx * WS + px + SHIFT; if (x >= RES) x -= RES;
    return b * (RES*RES) + y * RES + x;
}

__device__ __forceinline__ int region(int c) {
    return (c < RES - WS) ? 0 : ((c < RES - SHIFT) ? 1 : 2);
}

// ---------------- weight pre-round (fp32 -> tf32-rounded fp32) ----------------
__global__ void round_w(const float* __restrict__ s0, const float* __restrict__ s1,
                        const float* __restrict__ s2, const float* __restrict__ s3) {
    int i = blockIdx.x * blockDim.x + threadIdx.x;
    if (i >= W_TOTAL) return;
    float v;
    if      (i < W_PROJ_OFF) v = s0[i - W_QKV_OFF];
    else if (i < W_FC1_OFF)  v = s1[i - W_PROJ_OFF];
    else if (i < W_FC2_OFF)  v = s2[i - W_FC1_OFF];
    else                     v = s3[i - W_FC2_OFF];
    g_wr[i] = tfround(v);
}

// ---------------- LayerNorm (writes tf32-rounded output) ----------------
template<int GATHER>
__global__ void ln_kernel(const float* __restrict__ src, const float* __restrict__ g,
                          const float* __restrict__ bta, float* __restrict__ dst) {
    int tok  = blockIdx.x * 8 + (threadIdx.x >> 5);
    int lane = threadIdx.x & 31;
    if (tok >= TTOK) return;
    int srow = GATHER ? win_src_token(tok) : tok;
    const float* p = src + (size_t)srow * DIM;
    float v[6];
    float s = 0.f;
#pragma unroll
    for (int j = 0; j < 6; j++) { v[j] = p[j*32 + lane]; s += v[j]; }
#pragma unroll
    for (int o = 16; o; o >>= 1) s += __shfl_xor_sync(0xffffffffu, s, o);
    float mu = s * (1.f / DIM);
    float vr = 0.f;
#pragma unroll
    for (int j = 0; j < 6; j++) { float d = v[j] - mu; vr += d * d; }
#pragma unroll
    for (int o = 16; o; o >>= 1) vr += __shfl_xor_sync(0xffffffffu, vr, o);
    float r = rsqrtf(vr * (1.f / DIM) + 1e-5f);
    float* q = dst + (size_t)tok * DIM;
#pragma unroll
    for (int j = 0; j < 6; j++) {
        int c = j*32 + lane;
        q[c] = tfround((v[j] - mu) * r * g[c] + bta[c]);
    }
}

// ---------------- TF32 tensor-core GEMM, cp.async 3-stage, block 256x64 ----------------
__device__ __forceinline__ void mma8(float* c, const unsigned* a, const unsigned* b) {
    asm volatile("mma.sync.aligned.m16n8k8.row.col.f32.tf32.tf32.f32 "
        "{%0,%1,%2,%3},{%4,%5,%6,%7},{%8,%9},{%0,%1,%2,%3};"
        : "+f"(c[0]), "+f"(c[1]), "+f"(c[2]), "+f"(c[3])
        : "r"(a[0]), "r"(a[1]), "r"(a[2]), "r"(a[3]), "r"(b[0]), "r"(b[1]));
}

#define AST 12           // A smem row stride (8 k + 4 pad), 12 ≡ 4 mod 32
#define BST 72           // B smem k-row stride (64 n + 8 pad), 72 ≡ 8 mod 32
#define ASZ (256*AST)    // 3072 words per stage
#define BSZ (8*BST)      // 576 words per stage

template<int EPI>
__global__ __launch_bounds__(256, 2)
void gemm_tc(const float* __restrict__ A, const float* __restrict__ W,
             const float* __restrict__ bias, int K, int Nc,
             const float* __restrict__ extra_in,
             float* __restrict__ out, float* __restrict__ out2, float* __restrict__ out3) {
    __shared__ unsigned As[3][ASZ];
    __shared__ unsigned Bs[3][BSZ];

    int t    = threadIdx.x;
    int br   = blockIdx.y * 256;
    int bc   = blockIdx.x * 64;
    int lane = t & 31, warp = t >> 5;
    int wm   = warp & 3, wn = warp >> 2;       // 4 x 2 warps, warp tile 64x32
    int gid  = lane >> 2, tig = lane & 3;

    // cp.async source/dest (A: thread t owns row t of the block; 8 k = 2 x 16B)
    const float* aRow = A + (size_t)(br + t) * K;
    unsigned aDst = (unsigned)__cvta_generic_to_shared(&As[0][t * AST]);
    int bk = t >> 4, bn4 = (t & 15) * 4;       // threads 0..127 stage B
    unsigned bDst = (unsigned)__cvta_generic_to_shared(&Bs[0][bk * BST + bn4]);

    float acc[4][4][4];
#pragma unroll
    for (int mt = 0; mt < 4; mt++)
#pragma unroll
        for (int nt = 0; nt < 4; nt++)
#pragma unroll
            for (int e = 0; e < 4; e++) acc[mt][nt][e] = 0.f;

    int KT = K >> 3;

#define ISSUE(S, K0)                                                              \
    do {                                                                          \
        unsigned ad = aDst + (S) * (ASZ * 4);                                     \
        const float* ap = aRow + (K0);                                            \
        asm volatile("cp.async.cg.shared.global [%0], [%1], 16;\n"                \
                     :: "r"(ad), "l"(ap) : "memory");                             \
        asm volatile("cp.async.cg.shared.global [%0], [%1], 16;\n"                \
                     :: "r"(ad + 16), "l"(ap + 4) : "memory");                    \
        if (t < 128) {                                                            \
            const float* bp = W + (size_t)((K0) + bk) * Nc + bc + bn4;            \
            asm volatile("cp.async.cg.shared.global [%0], [%1], 16;\n"            \
                         :: "r"(bDst + (S) * (BSZ * 4)), "l"(bp) : "memory");     \
        }                                                                         \
        asm volatile("cp.async.commit_group;\n" ::: "memory");                    \
    } while (0)

    ISSUE(0, 0);
    ISSUE(1, 8);

    for (int kt = 0; kt < KT; kt++) {
        if (kt < KT - 1) asm volatile("cp.async.wait_group 1;\n" ::: "memory");
        else             asm volatile("cp.async.wait_group 0;\n" ::: "memory");
        __syncthreads();
        int snext = kt + 2;
        if (snext < KT) {
            int sn = snext - (snext / 3) * 3;
            ISSUE(sn, snext * 8);
        }
        int s = kt - (kt / 3) * 3;
        const unsigned* as = As[s];
        const unsigned* bs = Bs[s];

        unsigned a[4][4], b[4][2];
#pragma unroll
        for (int mt = 0; mt < 4; mt++) {
            int rb = wm*64 + mt*16 + gid;
            a[mt][0] = as[ rb      * AST + tig];
            a[mt][1] = as[(rb + 8) * AST + tig];
            a[mt][2] = as[ rb      * AST + tig + 4];
            a[mt][3] = as[(rb + 8) * AST + tig + 4];
        }
#pragma unroll
        for (int nt = 0; nt < 4; nt++) {
            int cb = wn*32 + nt*8 + gid;
            b[nt][0] = bs[ tig      * BST + cb];
            b[nt][1] = bs[(tig + 4) * BST + cb];
        }
#pragma unroll
        for (int mt = 0; mt < 4; mt++)
#pragma unroll
            for (int nt = 0; nt < 4; nt++) mma8(acc[mt][nt], a[mt], b[nt]);
    }
#undef ISSUE

    // epilogue
#pragma unroll
    for (int mt = 0; mt < 4; mt++) {
#pragma unroll
        for (int rr = 0; rr < 2; rr++) {
            int row = br + wm*64 + mt*16 + gid + rr*8;
            int dst = 0, win = 0, n = 0;
            if (EPI == 0) { win = row / NTOK; n = row - win * NTOK; }
            if (EPI == 1) { dst = win_src_token(row); }
#pragma unroll
            for (int nt = 0; nt < 4; nt++) {
#pragma unroll
                for (int cc = 0; cc < 2; cc++) {
                    int col = bc + wn*32 + nt*8 + tig*2 + cc;
                    float val = acc[mt][nt][rr*2 + cc] + __ldg(&bias[col]);
                    if (EPI == 0) {
                        int sseg = col / DIM;
                        int hh   = (col % DIM) >> 5;
                        int d    = col & 31;
                        size_t off = (((size_t)(win*HEADS + hh)) * NTOK + n) * HD + d;
                        if (sseg == 0)      out [off] = val * SCALE;
                        else if (sseg == 1) out2[off] = val;
                        else                out3[off] = val;
                    } else if (EPI == 1) {
                        size_t off = (size_t)dst * DIM + col;
                        out[off] = extra_in[off] + val;
                    } else if (EPI == 2) {
                        out[(size_t)row * (4*DIM) + col] =
                            tfround(0.5f * val * (1.f + erff(val * 0.70710678118654752f)));
                    } else {
                        size_t off = (size_t)row * DIM + col;
                        out[off] = val + extra_in[off];
                    }
                }
            }
        }
    }
}

// ---------------- attention: one block per (window, head) ----------------
__global__ __launch_bounds__(128)
void attn_kernel(const float* __restrict__ bias_table) {
    int bh   = blockIdx.x;
    int win  = bh / HEADS;
    int head = bh - win * HEADS;

    __shared__ float qs[NTOK*33];
    __shared__ float ks[NTOK*33];
    __shared__ float vs[NTOK*33];
    __shared__ float sc[NTOK][52];

    const float* qp = g_q + (size_t)bh * (NTOK*HD);
    const float* kp = g_k + (size_t)bh * (NTOK*HD);
    const float* vp = g_v + (size_t)bh * (NTOK*HD);

    int t = threadIdx.x;
    for (int i = t; i < NTOK*HD; i += 128) {
        int n = i >> 5, d = i & 31;
        qs[n*33 + d] = qp[i];
        ks[n*33 + d] = kp[i];
        vs[n*33 + d] = vp[i];
    }
    __syncthreads();

    int wi = win & 63;
    int wy = wi >> 3, wx = wi & 7;

    for (int idx = t; idx < NTOK*NTOK; idx += 128) {
        int i = idx / NTOK, j = idx - i * NTOK;
        float s = 0.f;
#pragma unroll
        for (int k2 = 0; k2 < HD; k2++) s = fmaf(qs[i*33 + k2], ks[j*33 + k2], s);
        int yi = i / WS, xi = i - yi*WS;
        int yj = j / WS, xj = j - yj*WS;
        int rel = (yi - yj + WS - 1) * (2*WS - 1) + (xi - xj + WS - 1);
        s += bias_table[rel * HEADS + head];
        int li = region(wy*WS + yi) * 3 + region(wx*WS + xi);
        int lj = region(wy*WS + yj) * 3 + region(wx*WS + xj);
        if (li != lj) s -= 100.f;
        sc[i][j] = s;
    }
    __syncthreads();

    int warp = t >> 5, lane = t & 31;
    for (int row = warp; row < NTOK; row += 4) {
        float a = (lane      < NTOK) ? sc[row][lane]      : -1e30f;
        float b = (lane + 32 < NTOK) ? sc[row][lane + 32] : -1e30f;
        float mx = fmaxf(a, b);
#pragma unroll
        for (int o = 16; o; o >>= 1) mx = fmaxf(mx, __shfl_xor_sync(0xffffffffu, mx, o));
        float ea = (lane      < NTOK) ? __expf(a - mx) : 0.f;
        float eb = (lane + 32 < NTOK) ? __expf(b - mx) : 0.f;
        float sum = ea + eb;
#pragma unroll
        for (int o = 16; o; o >>= 1) sum += __shfl_xor_sync(0xffffffffu, sum, o);
        float inv = 1.f / sum;
        if (lane      < NTOK) sc[row][lane]      = ea * inv;
        if (lane + 32 < NTOK) sc[row][lane + 32] = eb * inv;
    }
    __syncthreads();

    float* op = g_ao + ((size_t)win * NTOK) * DIM + head * HD;
    for (int idx = t; idx < NTOK*HD; idx += 128) {
        int i = idx >> 5, d = idx & 31;
        float s = 0.f;
#pragma unroll
        for (int j = 0; j < NTOK; j++) s = fmaf(sc[i][j], vs[j*33 + d], s);
        op[(size_t)i * DIM + d] = tfround(s);
    }
}

// ---------------- launch ----------------
static float* sym_ptr(const void* sym) {
    void* p = nullptr;
    cudaGetSymbolAddress(&p, sym);
    return (float*)p;
}

extern "C" void kernel_launch(void* const* d_in, const int* in_sizes, int n_in,
                              void* d_out, int out_size) {
    const float* x       = (const float*)d_in[0];
    const float* n1g     = (const float*)d_in[1];
    const float* n1b     = (const float*)d_in[2];
    const float* qkv_w   = (const float*)d_in[3];
    const float* qkv_b   = (const float*)d_in[4];
    const float* proj_w  = (const float*)d_in[5];
    const float* proj_b  = (const float*)d_in[6];
    const float* btab    = (const float*)d_in[7];
    const float* n2g     = (const float*)d_in[8];
    const float* n2b     = (const float*)d_in[9];
    const float* fc1_w   = (const float*)d_in[10];
    const float* fc1_b   = (const float*)d_in[11];
    const float* fc2_w   = (const float*)d_in[12];
    const float* fc2_b   = (const float*)d_in[13];
    float* outp = (float*)d_out;

    float* hln = sym_ptr(g_hln);
    float* q   = sym_ptr(g_q);
    float* k   = sym_ptr(g_k);
    float* v   = sym_ptr(g_v);
    float* ao  = sym_ptr(g_ao);
    float* xn  = sym_ptr(g_xn);
    float* ml  = sym_ptr(g_ml);
    float* wr  = sym_ptr(g_wr);

    // 0. pre-round weights to tf32
    round_w<<<(W_TOTAL + 255)/256, 256>>>(qkv_w, proj_w, fc1_w, fc2_w);
    // 1. LN1 + roll + window partition (rounded output)
    ln_kernel<1><<<TTOK/8, 256>>>(x, n1g, n1b, hln);
    // 2. qkv GEMM
    gemm_tc<0><<<dim3((3*DIM)/64, TTOK/256), 256>>>(hln, wr + W_QKV_OFF, qkv_b, DIM, 3*DIM,
                                                    nullptr, q, k, v);
    // 3. windowed attention
    attn_kernel<<<BW*HEADS, 128>>>(btab);
    // 4. proj GEMM + reverse scatter + residual
    gemm_tc<1><<<dim3(DIM/64, TTOK/256), 256>>>(ao, wr + W_PROJ_OFF, proj_b, DIM, DIM,
                                                x, xn, nullptr, nullptr);
    // 5. LN2
    ln_kernel<0><<<TTOK/8, 256>>>(xn, n2g, n2b, hln);
    // 6. fc1 GEMM + gelu
    gemm_tc<2><<<dim3((4*DIM)/64, TTOK/256), 256>>>(hln, wr + W_FC1_OFF, fc1_b, DIM, 4*DIM,
                                                    nullptr, ml, nullptr, nullptr);
    // 7. fc2 GEMM + residual -> output
    gemm_tc<3><<<dim3(DIM/64, TTOK/256), 256>>>(ml, wr + W_FC2_OFF, fc2_b, 4*DIM, DIM,
                                                xn, outp, nullptr, nullptr);
}

// round 5
// speedup vs baseline: 1.0284x; 1.0284x over previous
#include <cuda_runtime.h>
#include <math.h>

// ---------------- constants ----------------
#define RES   56
#define WS    7
#define SHIFT 3
#define DIM   192
#define HEADS 6
#define HD    32
#define NTOK  49
#define BATCH 32
#define NWIN  64
#define BW    (BATCH*NWIN)        // 2048 windows
#define TTOK  (BW*NTOK)           // 100352 rows
#define SCALE 0.17677669529663687f

#define W_QKV_OFF  0
#define W_QKV_N    (DIM*3*DIM)
#define W_PROJ_OFF (W_QKV_OFF + W_QKV_N)
#define W_PROJ_N   (DIM*DIM)
#define W_FC1_OFF  (W_PROJ_OFF + W_PROJ_N)
#define W_FC1_N    (DIM*4*DIM)
#define W_FC2_OFF  (W_FC1_OFF + W_FC1_N)
#define W_FC2_N    (4*DIM*DIM)
#define W_TOTAL    (W_FC2_OFF + W_FC2_N)

// ---------------- scratch ----------------
__device__ float g_hln[TTOK*DIM];
__device__ float g_q  [TTOK*DIM];
__device__ float g_k  [TTOK*DIM];
__device__ float g_v  [TTOK*DIM];
__device__ float g_ao [TTOK*DIM];
__device__ float g_xn [TTOK*DIM];
__device__ float g_ml [TTOK*4*DIM];
__device__ float g_wr [W_TOTAL];

__device__ __forceinline__ unsigned f2tf(float x) {
    unsigned r; asm("cvt.rna.tf32.f32 %0, %1;" : "=r"(r) : "f"(x)); return r;
}
__device__ __forceinline__ float tfround(float x) { return __uint_as_float(f2tf(x)); }

__device__ __forceinline__ int win_src_token(int m) {
    int win = m / NTOK, n = m - win * NTOK;
    int b   = win >> 6, wi = win & 63;
    int wy  = wi >> 3,  wx = wi & 7;
    int py  = n / WS,   px = n - py * WS;
    int y = wy * WS + py + SHIFT; if (y >= RES) y -= RES;
    int x = wx * WS + px + SHIFT; if (x >= RES) x -= RES;
    return b * (RES*RES) + y * RES + x;
}

__device__ __forceinline__ int region(int c) {
    return (c < RES - WS) ? 0 : ((c < RES - SHIFT) ? 1 : 2);
}

// ---------------- weight pre-round ----------------
__global__ void round_w(const float* __restrict__ s0, const float* __restrict__ s1,
                        const float* __restrict__ s2, const float* __restrict__ s3) {
    int i = blockIdx.x * blockDim.x + threadIdx.x;
    if (i >= W_TOTAL) return;
    float v;
    if      (i < W_PROJ_OFF) v = s0[i - W_QKV_OFF];
    else if (i < W_FC1_OFF)  v = s1[i - W_PROJ_OFF];
    else if (i < W_FC2_OFF)  v = s2[i - W_FC1_OFF];
    else                     v = s3[i - W_FC2_OFF];
    g_wr[i] = tfround(v);
}

// ---------------- LayerNorm ----------------
template<int GATHER>
__global__ void ln_kernel(const float* __restrict__ src, const float* __restrict__ g,
                          const float* __restrict__ bta, float* __restrict__ dst) {
    int tok  = blockIdx.x * 8 + (threadIdx.x >> 5);
    int lane = threadIdx.x & 31;
    if (tok >= TTOK) return;
    int srow = GATHER ? win_src_token(tok) : tok;
    const float* p = src + (size_t)srow * DIM;
    float v[6];
    float s = 0.f;
#pragma unroll
    for (int j = 0; j < 6; j++) { v[j] = p[j*32 + lane]; s += v[j]; }
#pragma unroll
    for (int o = 16; o; o >>= 1) s += __shfl_xor_sync(0xffffffffu, s, o);
    float mu = s * (1.f / DIM);
    float vr = 0.f;
#pragma unroll
    for (int j = 0; j < 6; j++) { float d = v[j] - mu; vr += d * d; }
#pragma unroll
    for (int o = 16; o; o >>= 1) vr += __shfl_xor_sync(0xffffffffu, vr, o);
    float r = rsqrtf(vr * (1.f / DIM) + 1e-5f);
    float* q = dst + (size_t)tok * DIM;
#pragma unroll
    for (int j = 0; j < 6; j++) {
        int c = j*32 + lane;
        q[c] = tfround((v[j] - mu) * r * g[c] + bta[c]);
    }
}

// ---------------- TF32 MMA primitive ----------------
__device__ __forceinline__ void mma8(float* c, const unsigned* a, const unsigned* b) {
    asm volatile("mma.sync.aligned.m16n8k8.row.col.f32.tf32.tf32.f32 "
        "{%0,%1,%2,%3},{%4,%5,%6,%7},{%8,%9},{%0,%1,%2,%3};"
        : "+f"(c[0]), "+f"(c[1]), "+f"(c[2]), "+f"(c[3])
        : "r"(a[0]), "r"(a[1]), "r"(a[2]), "r"(a[3]), "r"(b[0]), "r"(b[1]));
}

// ---------------- TF32 GEMM, cp.async 3-stage, block 256x64 ----------------
#define AST 12
#define BST 72
#define ASZ (256*AST)
#define BSZ (8*BST)

template<int EPI>
__global__ __launch_bounds__(256, 2)
void gemm_tc(const float* __restrict__ A, const float* __restrict__ W,
             const float* __restrict__ bias, int K, int Nc,
             const float* __restrict__ extra_in,
             float* __restrict__ out, float* __restrict__ out2, float* __restrict__ out3) {
    __shared__ unsigned As[3][ASZ];
    __shared__ unsigned Bs[3][BSZ];

    int t    = threadIdx.x;
    int br   = blockIdx.y * 256;
    int bc   = blockIdx.x * 64;
    int lane = t & 31, warp = t >> 5;
    int wm   = warp & 3, wn = warp >> 2;
    int gid  = lane >> 2, tig = lane & 3;

    const float* aRow = A + (size_t)(br + t) * K;
    unsigned aDst = (unsigned)__cvta_generic_to_shared(&As[0][t * AST]);
    int bk = t >> 4, bn4 = (t & 15) * 4;
    unsigned bDst = (unsigned)__cvta_generic_to_shared(&Bs[0][bk * BST + bn4]);

    float acc[4][4][4];
#pragma unroll
    for (int mt = 0; mt < 4; mt++)
#pragma unroll
        for (int nt = 0; nt < 4; nt++)
#pragma unroll
            for (int e = 0; e < 4; e++) acc[mt][nt][e] = 0.f;

    int KT = K >> 3;

#define ISSUE(S, K0)                                                              \
    do {                                                                          \
        unsigned ad = aDst + (S) * (ASZ * 4);                                     \
        const float* ap = aRow + (K0);                                            \
        asm volatile("cp.async.cg.shared.global [%0], [%1], 16;\n"                \
                     :: "r"(ad), "l"(ap) : "memory");                             \
        asm volatile("cp.async.cg.shared.global [%0], [%1], 16;\n"                \
                     :: "r"(ad + 16), "l"(ap + 4) : "memory");                    \
        if (t < 128) {                                                            \
            const float* bp = W + (size_t)((K0) + bk) * Nc + bc + bn4;            \
            asm volatile("cp.async.cg.shared.global [%0], [%1], 16;\n"            \
                         :: "r"(bDst + (S) * (BSZ * 4)), "l"(bp) : "memory");     \
        }                                                                         \
        asm volatile("cp.async.commit_group;\n" ::: "memory");                    \
    } while (0)

    ISSUE(0, 0);
    ISSUE(1, 8);

    for (int kt = 0; kt < KT; kt++) {
        if (kt < KT - 1) asm volatile("cp.async.wait_group 1;\n" ::: "memory");
        else             asm volatile("cp.async.wait_group 0;\n" ::: "memory");
        __syncthreads();
        int snext = kt + 2;
        if (snext < KT) {
            int sn = snext - (snext / 3) * 3;
            ISSUE(sn, snext * 8);
        }
        int s = kt - (kt / 3) * 3;
        const unsigned* as = As[s];
        const unsigned* bs = Bs[s];

        unsigned a[4][4], b[4][2];
#pragma unroll
        for (int mt = 0; mt < 4; mt++) {
            int rb = wm*64 + mt*16 + gid;
            a[mt][0] = as[ rb      * AST + tig];
            a[mt][1] = as[(rb + 8) * AST + tig];
            a[mt][2] = as[ rb      * AST + tig + 4];
            a[mt][3] = as[(rb + 8) * AST + tig + 4];
        }
#pragma unroll
        for (int nt = 0; nt < 4; nt++) {
            int cb = wn*32 + nt*8 + gid;
            b[nt][0] = bs[ tig      * BST + cb];
            b[nt][1] = bs[(tig + 4) * BST + cb];
        }
#pragma unroll
        for (int mt = 0; mt < 4; mt++)
#pragma unroll
            for (int nt = 0; nt < 4; nt++) mma8(acc[mt][nt], a[mt], b[nt]);
    }
#undef ISSUE

#pragma unroll
    for (int mt = 0; mt < 4; mt++) {
#pragma unroll
        for (int rr = 0; rr < 2; rr++) {
            int row = br + wm*64 + mt*16 + gid + rr*8;
            int dst = 0, win = 0, n = 0;
            if (EPI == 0) { win = row / NTOK; n = row - win * NTOK; }
            if (EPI == 1) { dst = win_src_token(row); }
#pragma unroll
            for (int nt = 0; nt < 4; nt++) {
#pragma unroll
                for (int cc = 0; cc < 2; cc++) {
                    int col = bc + wn*32 + nt*8 + tig*2 + cc;
                    float val = acc[mt][nt][rr*2 + cc] + __ldg(&bias[col]);
                    if (EPI == 0) {
                        int sseg = col / DIM;
                        int hh   = (col % DIM) >> 5;
                        int d    = col & 31;
                        size_t off = (((size_t)(win*HEADS + hh)) * NTOK + n) * HD + d;
                        if (sseg == 0)      out [off] = val * SCALE;
                        else if (sseg == 1) out2[off] = val;
                        else                out3[off] = val;
                    } else if (EPI == 1) {
                        size_t off = (size_t)dst * DIM + col;
                        out[off] = extra_in[off] + val;
                    } else if (EPI == 2) {
                        out[(size_t)row * (4*DIM) + col] =
                            tfround(0.5f * val * (1.f + erff(val * 0.70710678118654752f)));
                    } else {
                        size_t off = (size_t)row * DIM + col;
                        out[off] = val + extra_in[off];
                    }
                }
            }
        }
    }
}

// ---------------- attention: tensor-core MMA, one block per (window, head) ----------------
// 4 warps; warp w owns rows [w*16, w*16+16) of the padded 64x56 score tile.
__global__ __launch_bounds__(128)
void attn_kernel(const float* __restrict__ bias_table) {
    int bh   = blockIdx.x;
    int win  = bh / HEADS;
    int head = bh - win * HEADS;

    __shared__ float qs[64][36];   // stride 36: frag loads conflict-free
    __shared__ float ksm[56][36];
    __shared__ float vsm[56][36];
    __shared__ float sc[64][60];   // stride 60: frag + softmax conflict-free

    const float* qp = g_q + (size_t)bh * (NTOK*HD);
    const float* kp = g_k + (size_t)bh * (NTOK*HD);
    const float* vp = g_v + (size_t)bh * (NTOK*HD);

    int t = threadIdx.x;
    // zero score tile (padding cols must be 0 for P@V)
    float* scf = &sc[0][0];
    for (int i = t; i < 64*60; i += 128) scf[i] = 0.f;
    for (int i = t; i < 64*HD; i += 128) {
        int r = i >> 5, d = i & 31;
        qs[r][d] = (r < NTOK) ? tfround(qp[i]) : 0.f;
    }
    for (int i = t; i < 56*HD; i += 128) {
        int r = i >> 5, d = i & 31;
        bool ok = (r < NTOK);
        ksm[r][d] = ok ? tfround(kp[i]) : 0.f;
        vsm[r][d] = ok ? tfround(vp[i]) : 0.f;
    }
    __syncthreads();

    int lane = t & 31, warp = t >> 5;
    int gid  = lane >> 2, tig = lane & 3;
    int row0 = warp * 16 + gid;

    // ---- S = Q @ K^T  (64x56, K=32) ----
    float acc[7][4];
#pragma unroll
    for (int nt = 0; nt < 7; nt++)
#pragma unroll
        for (int e = 0; e < 4; e++) acc[nt][e] = 0.f;

#pragma unroll
    for (int k8 = 0; k8 < 4; k8++) {
        int kk = k8*8 + tig;
        unsigned a[4];
        a[0] = __float_as_uint(qs[row0    ][kk    ]);
        a[1] = __float_as_uint(qs[row0 + 8][kk    ]);
        a[2] = __float_as_uint(qs[row0    ][kk + 4]);
        a[3] = __float_as_uint(qs[row0 + 8][kk + 4]);
#pragma unroll
        for (int nt = 0; nt < 7; nt++) {
            unsigned b[2];
            b[0] = __float_as_uint(ksm[nt*8 + gid][kk    ]);
            b[1] = __float_as_uint(ksm[nt*8 + gid][kk + 4]);
            mma8(acc[nt], a, b);
        }
    }

    // score epilogue: bias + shift mask, store to sc
    int wi = win & 63;
    int wy = wi >> 3, wx = wi & 7;
#pragma unroll
    for (int nt = 0; nt < 7; nt++) {
#pragma unroll
        for (int e = 0; e < 4; e++) {
            int i = row0 + ((e >= 2) ? 8 : 0);
            int j = nt*8 + tig*2 + (e & 1);
            if (i < NTOK && j < NTOK) {
                int yi = i / WS, xi = i - yi*WS;
                int yj = j / WS, xj = j - yj*WS;
                int rel = (yi - yj + WS - 1) * (2*WS - 1) + (xi - xj + WS - 1);
                float s = acc[nt][e] + bias_table[rel * HEADS + head];
                int li = region(wy*WS + yi) * 3 + region(wx*WS + xi);
                int lj = region(wy*WS + yj) * 3 + region(wx*WS + xj);
                if (li != lj) s -= 100.f;
                sc[i][j] = s;
            }
        }
    }
    __syncthreads();

    // ---- softmax over rows, write tf32-rounded P ----
    for (int row = warp; row < NTOK; row += 4) {
        float a = (lane      < NTOK) ? sc[row][lane]      : -1e30f;
        float b = (lane + 32 < NTOK) ? sc[row][lane + 32] : -1e30f;
        float mx = fmaxf(a, b);
#pragma unroll
        for (int o = 16; o; o >>= 1) mx = fmaxf(mx, __shfl_xor_sync(0xffffffffu, mx, o));
        float ea = (lane      < NTOK) ? __expf(a - mx) : 0.f;
        float eb = (lane + 32 < NTOK) ? __expf(b - mx) : 0.f;
        float sum = ea + eb;
#pragma unroll
        for (int o = 16; o; o >>= 1) sum += __shfl_xor_sync(0xffffffffu, sum, o);
        float inv = 1.f / sum;
        if (lane      < NTOK) sc[row][lane]      = tfround(ea * inv);
        if (lane + 32 < NTOK) sc[row][lane + 32] = tfround(eb * inv);
    }
    __syncthreads();

    // ---- O = P @ V  (64x32, K=56) ----
    float oacc[4][4];
#pragma unroll
    for (int nt = 0; nt < 4; nt++)
#pragma unroll
        for (int e = 0; e < 4; e++) oacc[nt][e] = 0.f;

#pragma unroll
    for (int k7 = 0; k7 < 7; k7++) {
        int kk = k7*8 + tig;
        unsigned a[4];
        a[0] = __float_as_uint(sc[row0    ][kk    ]);
        a[1] = __float_as_uint(sc[row0 + 8][kk    ]);
        a[2] = __float_as_uint(sc[row0    ][kk + 4]);
        a[3] = __float_as_uint(sc[row0 + 8][kk + 4]);
#pragma unroll
        for (int nt = 0; nt < 4; nt++) {
            unsigned b[2];
            b[0] = __float_as_uint(vsm[kk    ][nt*8 + gid]);
            b[1] = __float_as_uint(vsm[kk + 4][nt*8 + gid]);
            mma8(oacc[nt], a, b);
        }
    }

    float* op = g_ao + ((size_t)win * NTOK) * DIM + head * HD;
#pragma unroll
    for (int nt = 0; nt < 4; nt++) {
#pragma unroll
        for (int e = 0; e < 4; e++) {
            int i = row0 + ((e >= 2) ? 8 : 0);
            int d = nt*8 + tig*2 + (e & 1);
            if (i < NTOK) op[(size_t)i * DIM + d] = tfround(oacc[nt][e]);
        }
    }
}

// ---------------- launch ----------------
static float* sym_ptr(const void* sym) {
    void* p = nullptr;
    cudaGetSymbolAddress(&p, sym);
    return (float*)p;
}

extern "C" void kernel_launch(void* const* d_in, const int* in_sizes, int n_in,
                              void* d_out, int out_size) {
    const float* x       = (const float*)d_in[0];
    const float* n1g     = (const float*)d_in[1];
    const float* n1b     = (const float*)d_in[2];
    const float* qkv_w   = (const float*)d_in[3];
    const float* qkv_b   = (const float*)d_in[4];
    const float* proj_w  = (const float*)d_in[5];
    const float* proj_b  = (const float*)d_in[6];
    const float* btab    = (const float*)d_in[7];
    const float* n2g     = (const float*)d_in[8];
    const float* n2b     = (const float*)d_in[9];
    const float* fc1_w   = (const float*)d_in[10];
    const float* fc1_b   = (const float*)d_in[11];
    const float* fc2_w   = (const float*)d_in[12];
    const float* fc2_b   = (const float*)d_in[13];
    float* outp = (float*)d_out;

    float* hln = sym_ptr(g_hln);
    float* q   = sym_ptr(g_q);
    float* k   = sym_ptr(g_k);
    float* v   = sym_ptr(g_v);
    float* ao  = sym_ptr(g_ao);
    float* xn  = sym_ptr(g_xn);
    float* ml  = sym_ptr(g_ml);
    float* wr  = sym_ptr(g_wr);

    round_w<<<(W_TOTAL + 255)/256, 256>>>(qkv_w, proj_w, fc1_w, fc2_w);
    ln_kernel<1><<<TTOK/8, 256>>>(x, n1g, n1b, hln);
    gemm_tc<0><<<dim3((3*DIM)/64, TTOK/256), 256>>>(hln, wr + W_QKV_OFF, qkv_b, DIM, 3*DIM,
                                                    nullptr, q, k, v);
    attn_kernel<<<BW*HEADS, 128>>>(btab);
    gemm_tc<1><<<dim3(DIM/64, TTOK/256), 256>>>(ao, wr + W_PROJ_OFF, proj_b, DIM, DIM,
                                                x, xn, nullptr, nullptr);
    ln_kernel<0><<<TTOK/8, 256>>>(xn, n2g, n2b, hln);
    gemm_tc<2><<<dim3((4*DIM)/64, TTOK/256), 256>>>(hln, wr + W_FC1_OFF, fc1_b, DIM, 4*DIM,
                                                    nullptr, ml, nullptr, nullptr);
    gemm_tc<3><<<dim3(DIM/64, TTOK/256), 256>>>(ml, wr + W_FC2_OFF, fc2_b, 4*DIM, DIM,
                                                xn, outp, nullptr, nullptr);
}

// round 6
// speedup vs baseline: 1.2151x; 1.1816x over previous
#include <cuda_runtime.h>
#include <math.h>

// ---------------- constants ----------------
#define RES   56
#define WS    7
#define SHIFT 3
#define DIM   192
#define HEADS 6
#define HD    32
#define NTOK  49
#define BATCH 32
#define NWIN  64
#define BW    (BATCH*NWIN)        // 2048 windows
#define TTOK  (BW*NTOK)           // 100352 rows
#define SCALE 0.17677669529663687f

#define W_QKV_OFF  0
#define W_QKV_N    (DIM*3*DIM)
#define W_PROJ_OFF (W_QKV_OFF + W_QKV_N)
#define W_PROJ_N   (DIM*DIM)
#define W_FC1_OFF  (W_PROJ_OFF + W_PROJ_N)
#define W_FC1_N    (DIM*4*DIM)
#define W_FC2_OFF  (W_FC1_OFF + W_FC1_N)
#define W_FC2_N    (4*DIM*DIM)
#define W_TOTAL    (W_FC2_OFF + W_FC2_N)

// ---------------- scratch ----------------
__device__ float g_hln[TTOK*DIM];
__device__ float g_q  [TTOK*DIM];
__device__ float g_k  [TTOK*DIM];
__device__ float g_v  [TTOK*DIM];
__device__ float g_ao [TTOK*DIM];
__device__ float g_xn [TTOK*DIM];
__device__ float g_ml [TTOK*4*DIM];
__device__ float g_wr [W_TOTAL];

__device__ __forceinline__ unsigned f2tf(float x) {
    unsigned r; asm("cvt.rna.tf32.f32 %0, %1;" : "=r"(r) : "f"(x)); return r;
}
__device__ __forceinline__ float tfround(float x) { return __uint_as_float(f2tf(x)); }

__device__ __forceinline__ int win_src_token(int m) {
    int win = m / NTOK, n = m - win * NTOK;
    int b   = win >> 6, wi = win & 63;
    int wy  = wi >> 3,  wx = wi & 7;
    int py  = n / WS,   px = n - py * WS;
    int y = wy * WS + py + SHIFT; if (y >= RES) y -= RES;
    int x = wx * WS + px + SHIFT; if (x >= RES) x -= RES;
    return b * (RES*RES) + y * RES + x;
}

__device__ __forceinline__ int region(int c) {
    return (c < RES - WS) ? 0 : ((c < RES - SHIFT) ? 1 : 2);
}

// ---------------- weight pre-round ----------------
__global__ void round_w(const float* __restrict__ s0, const float* __restrict__ s1,
                        const float* __restrict__ s2, const float* __restrict__ s3) {
    int i = blockIdx.x * blockDim.x + threadIdx.x;
    if (i >= W_TOTAL) return;
    float v;
    if      (i < W_PROJ_OFF) v = s0[i - W_QKV_OFF];
    else if (i < W_FC1_OFF)  v = s1[i - W_PROJ_OFF];
    else if (i < W_FC2_OFF)  v = s2[i - W_FC1_OFF];
    else                     v = s3[i - W_FC2_OFF];
    g_wr[i] = tfround(v);
}

// ---------------- LayerNorm ----------------
template<int GATHER>
__global__ void ln_kernel(const float* __restrict__ src, const float* __restrict__ g,
                          const float* __restrict__ bta, float* __restrict__ dst) {
    int tok  = blockIdx.x * 8 + (threadIdx.x >> 5);
    int lane = threadIdx.x & 31;
    if (tok >= TTOK) return;
    int srow = GATHER ? win_src_token(tok) : tok;
    const float* p = src + (size_t)srow * DIM;
    float v[6];
    float s = 0.f;
#pragma unroll
    for (int j = 0; j < 6; j++) { v[j] = p[j*32 + lane]; s += v[j]; }
#pragma unroll
    for (int o = 16; o; o >>= 1) s += __shfl_xor_sync(0xffffffffu, s, o);
    float mu = s * (1.f / DIM);
    float vr = 0.f;
#pragma unroll
    for (int j = 0; j < 6; j++) { float d = v[j] - mu; vr += d * d; }
#pragma unroll
    for (int o = 16; o; o >>= 1) vr += __shfl_xor_sync(0xffffffffu, vr, o);
    float r = rsqrtf(vr * (1.f / DIM) + 1e-5f);
    float* q = dst + (size_t)tok * DIM;
#pragma unroll
    for (int j = 0; j < 6; j++) {
        int c = j*32 + lane;
        q[c] = tfround((v[j] - mu) * r * g[c] + bta[c]);
    }
}

// ---------------- TF32 MMA primitive ----------------
__device__ __forceinline__ void mma8(float* c, const unsigned* a, const unsigned* b) {
    asm volatile("mma.sync.aligned.m16n8k8.row.col.f32.tf32.tf32.f32 "
        "{%0,%1,%2,%3},{%4,%5,%6,%7},{%8,%9},{%0,%1,%2,%3};"
        : "+f"(c[0]), "+f"(c[1]), "+f"(c[2]), "+f"(c[3])
        : "r"(a[0]), "r"(a[1]), "r"(a[2]), "r"(a[3]), "r"(b[0]), "r"(b[1]));
}

// ---------------- TF32 GEMM, cp.async 3-stage, block 256x64 (unchanged) ----------------
#define AST 12
#define BST 72
#define ASZ (256*AST)
#define BSZ (8*BST)

template<int EPI>
__global__ __launch_bounds__(256, 2)
void gemm_tc(const float* __restrict__ A, const float* __restrict__ W,
             const float* __restrict__ bias, int K, int Nc,
             const float* __restrict__ extra_in,
             float* __restrict__ out, float* __restrict__ out2, float* __restrict__ out3) {
    __shared__ unsigned As[3][ASZ];
    __shared__ unsigned Bs[3][BSZ];

    int t    = threadIdx.x;
    int br   = blockIdx.y * 256;
    int bc   = blockIdx.x * 64;
    int lane = t & 31, warp = t >> 5;
    int wm   = warp & 3, wn = warp >> 2;
    int gid  = lane >> 2, tig = lane & 3;

    const float* aRow = A + (size_t)(br + t) * K;
    unsigned aDst = (unsigned)__cvta_generic_to_shared(&As[0][t * AST]);
    int bk = t >> 4, bn4 = (t & 15) * 4;
    unsigned bDst = (unsigned)__cvta_generic_to_shared(&Bs[0][bk * BST + bn4]);

    float acc[4][4][4];
#pragma unroll
    for (int mt = 0; mt < 4; mt++)
#pragma unroll
        for (int nt = 0; nt < 4; nt++)
#pragma unroll
            for (int e = 0; e < 4; e++) acc[mt][nt][e] = 0.f;

    int KT = K >> 3;

#define ISSUE(S, K0)                                                              \
    do {                                                                          \
        unsigned ad = aDst + (S) * (ASZ * 4);                                     \
        const float* ap = aRow + (K0);                                            \
        asm volatile("cp.async.cg.shared.global [%0], [%1], 16;\n"                \
                     :: "r"(ad), "l"(ap) : "memory");                             \
        asm volatile("cp.async.cg.shared.global [%0], [%1], 16;\n"                \
                     :: "r"(ad + 16), "l"(ap + 4) : "memory");                    \
        if (t < 128) {                                                            \
            const float* bp = W + (size_t)((K0) + bk) * Nc + bc + bn4;            \
            asm volatile("cp.async.cg.shared.global [%0], [%1], 16;\n"            \
                         :: "r"(bDst + (S) * (BSZ * 4)), "l"(bp) : "memory");     \
        }                                                                         \
        asm volatile("cp.async.commit_group;\n" ::: "memory");                    \
    } while (0)

    ISSUE(0, 0);
    ISSUE(1, 8);

    for (int kt = 0; kt < KT; kt++) {
        if (kt < KT - 1) asm volatile("cp.async.wait_group 1;\n" ::: "memory");
        else             asm volatile("cp.async.wait_group 0;\n" ::: "memory");
        __syncthreads();
        int snext = kt + 2;
        if (snext < KT) {
            int sn = snext - (snext / 3) * 3;
            ISSUE(sn, snext * 8);
        }
        int s = kt - (kt / 3) * 3;
        const unsigned* as = As[s];
        const unsigned* bs = Bs[s];

        unsigned a[4][4], b[4][2];
#pragma unroll
        for (int mt = 0; mt < 4; mt++) {
            int rb = wm*64 + mt*16 + gid;
            a[mt][0] = as[ rb      * AST + tig];
            a[mt][1] = as[(rb + 8) * AST + tig];
            a[mt][2] = as[ rb      * AST + tig + 4];
            a[mt][3] = as[(rb + 8) * AST + tig + 4];
        }
#pragma unroll
        for (int nt = 0; nt < 4; nt++) {
            int cb = wn*32 + nt*8 + gid;
            b[nt][0] = bs[ tig      * BST + cb];
            b[nt][1] = bs[(tig + 4) * BST + cb];
        }
#pragma unroll
        for (int mt = 0; mt < 4; mt++)
#pragma unroll
            for (int nt = 0; nt < 4; nt++) mma8(acc[mt][nt], a[mt], b[nt]);
    }
#undef ISSUE

#pragma unroll
    for (int mt = 0; mt < 4; mt++) {
#pragma unroll
        for (int rr = 0; rr < 2; rr++) {
            int row = br + wm*64 + mt*16 + gid + rr*8;
            int dst = 0, win = 0, n = 0;
            if (EPI == 0) { win = row / NTOK; n = row - win * NTOK; }
            if (EPI == 1) { dst = win_src_token(row); }
#pragma unroll
            for (int nt = 0; nt < 4; nt++) {
#pragma unroll
                for (int cc = 0; cc < 2; cc++) {
                    int col = bc + wn*32 + nt*8 + tig*2 + cc;
                    float val = acc[mt][nt][rr*2 + cc] + __ldg(&bias[col]);
                    if (EPI == 0) {
                        int sseg = col / DIM;
                        int hh   = (col % DIM) >> 5;
                        int d    = col & 31;
                        size_t off = (((size_t)(win*HEADS + hh)) * NTOK + n) * HD + d;
                        if (sseg == 0)      out [off] = val * SCALE;
                        else if (sseg == 1) out2[off] = val;
                        else                out3[off] = val;
                    } else if (EPI == 1) {
                        size_t off = (size_t)dst * DIM + col;
                        out[off] = extra_in[off] + val;
                    } else if (EPI == 2) {
                        out[(size_t)row * (4*DIM) + col] =
                            tfround(0.5f * val * (1.f + erff(val * 0.70710678118654752f)));
                    } else {
                        size_t off = (size_t)row * DIM + col;
                        out[off] = val + extra_in[off];
                    }
                }
            }
        }
    }
}

// ---------------- attention: register-resident softmax + shfl permute ----------------
// One block per (window, head); 4 warps; warp w owns rows [w*16, w*16+16).
// No score tile in smem: softmax on C-fragments via tig-group shfl; P relayout
// for P@V via register shuffle.
__global__ __launch_bounds__(128, 6)
void attn_kernel(const float* __restrict__ bias_table) {
    int bh   = blockIdx.x;
    int win  = bh / HEADS;
    int head = bh - win * HEADS;

    __shared__ float qs [64][36];
    __shared__ float ksm[56][36];
    __shared__ float vsm[56][40];

    const float* qp = g_q + (size_t)bh * (NTOK*HD);
    const float* kp = g_k + (size_t)bh * (NTOK*HD);
    const float* vp = g_v + (size_t)bh * (NTOK*HD);

    int t = threadIdx.x;
    // zero V pad rows 49..55 (must be finite: P cols there are 0, 0*NaN=NaN)
    if (t < 224) vsm[NTOK + (t >> 5)][t & 31] = 0.f;
    // stage q/k/v (float4 chunks; 392 chunks each)
    for (int c = t; c < 392; c += 128) {
        int r = c >> 3, kq = (c & 7) * 4;
        float4 fq = *(const float4*)(qp + r*HD + kq);
        float4 fk = *(const float4*)(kp + r*HD + kq);
        float4 fv = *(const float4*)(vp + r*HD + kq);
        *(float4*)&qs [r][kq] = fq;
        *(float4*)&ksm[r][kq] = fk;
        *(float4*)&vsm[r][kq] = fv;
    }
    __syncthreads();

    int lane = t & 31, warp = t >> 5;
    int gid  = lane >> 2, tig = lane & 3;
    int row0 = warp * 16 + gid;
    int row_lo = row0, row_hi = row0 + 8;

    // ---- S = Q @ K^T (64x56, K=32) ----
    float acc[7][4];
#pragma unroll
    for (int nt = 0; nt < 7; nt++)
#pragma unroll
        for (int e = 0; e < 4; e++) acc[nt][e] = 0.f;

#pragma unroll
    for (int k8 = 0; k8 < 4; k8++) {
        int kk = k8*8 + tig;
        unsigned a[4];
        a[0] = __float_as_uint(qs[row_lo][kk    ]);
        a[1] = __float_as_uint(qs[row_hi][kk    ]);
        a[2] = __float_as_uint(qs[row_lo][kk + 4]);
        a[3] = __float_as_uint(qs[row_hi][kk + 4]);
#pragma unroll
        for (int nt = 0; nt < 7; nt++) {
            unsigned b[2];
            b[0] = __float_as_uint(ksm[nt*8 + gid][kk    ]);
            b[1] = __float_as_uint(ksm[nt*8 + gid][kk + 4]);
            mma8(acc[nt], a, b);
        }
    }

    // ---- bias + shift mask in registers ----
    int wi = win & 63;
    int wy = wi >> 3, wx = wi & 7;
#pragma unroll
    for (int nt = 0; nt < 7; nt++) {
#pragma unroll
        for (int e = 0; e < 4; e++) {
            int i = (e >= 2) ? row_hi : row_lo;
            int j = nt*8 + tig*2 + (e & 1);
            if (i < NTOK && j < NTOK) {
                int yi = i / WS, xi = i - yi*WS;
                int yj = j / WS, xj = j - yj*WS;
                int rel = (yi - yj + WS - 1) * (2*WS - 1) + (xi - xj + WS - 1);
                float s = acc[nt][e] + __ldg(&bias_table[rel * HEADS + head]);
                int li = region(wy*WS + yi) * 3 + region(wx*WS + xi);
                int lj = region(wy*WS + yj) * 3 + region(wx*WS + xj);
                if (li != lj) s -= 100.f;
                acc[nt][e] = s;
            } else {
                acc[nt][e] = -1e30f;
            }
        }
    }

    // ---- softmax in registers (row spread across tig group of 4 lanes) ----
    float m0 = -1e30f, m1 = -1e30f;
#pragma unroll
    for (int nt = 0; nt < 7; nt++) {
        m0 = fmaxf(m0, fmaxf(acc[nt][0], acc[nt][1]));
        m1 = fmaxf(m1, fmaxf(acc[nt][2], acc[nt][3]));
    }
    m0 = fmaxf(m0, __shfl_xor_sync(0xffffffffu, m0, 1));
    m0 = fmaxf(m0, __shfl_xor_sync(0xffffffffu, m0, 2));
    m1 = fmaxf(m1, __shfl_xor_sync(0xffffffffu, m1, 1));
    m1 = fmaxf(m1, __shfl_xor_sync(0xffffffffu, m1, 2));
    float s0 = 0.f, s1 = 0.f;
#pragma unroll
    for (int nt = 0; nt < 7; nt++) {
        acc[nt][0] = __expf(acc[nt][0] - m0); s0 += acc[nt][0];
        acc[nt][1] = __expf(acc[nt][1] - m0); s0 += acc[nt][1];
        acc[nt][2] = __expf(acc[nt][2] - m1); s1 += acc[nt][2];
        acc[nt][3] = __expf(acc[nt][3] - m1); s1 += acc[nt][3];
    }
    s0 += __shfl_xor_sync(0xffffffffu, s0, 1);
    s0 += __shfl_xor_sync(0xffffffffu, s0, 2);
    s1 += __shfl_xor_sync(0xffffffffu, s1, 1);
    s1 += __shfl_xor_sync(0xffffffffu, s1, 2);
    float inv0 = 1.f / s0, inv1 = 1.f / s1;
#pragma unroll
    for (int nt = 0; nt < 7; nt++) {
        acc[nt][0] *= inv0; acc[nt][1] *= inv0;
        acc[nt][2] *= inv1; acc[nt][3] *= inv1;
    }

    // ---- O = P @ V (64x32, K=56); P via register shuffle relayout ----
    float oacc[4][4];
#pragma unroll
    for (int nt = 0; nt < 4; nt++)
#pragma unroll
        for (int e = 0; e < 4; e++) oacc[nt][e] = 0.f;

    int base = lane & ~3;
    int sl0  = base + (tig >> 1);      // source lane for cols tig
    int sl1  = sl0 + 2;                // source lane for cols tig+4
    int odd  = tig & 1;

#pragma unroll
    for (int k7 = 0; k7 < 7; k7++) {
        float x0 = acc[k7][0], x1 = acc[k7][1];   // row_lo, cols 2tig, 2tig+1
        float y0 = acc[k7][2], y1 = acc[k7][3];   // row_hi
        float t0, t1;
        unsigned a[4];
        t0 = __shfl_sync(0xffffffffu, x0, sl0);
        t1 = __shfl_sync(0xffffffffu, x1, sl0);
        a[0] = __float_as_uint(odd ? t1 : t0);
        t0 = __shfl_sync(0xffffffffu, y0, sl0);
        t1 = __shfl_sync(0xffffffffu, y1, sl0);
        a[1] = __float_as_uint(odd ? t1 : t0);
        t0 = __shfl_sync(0xffffffffu, x0, sl1);
        t1 = __shfl_sync(0xffffffffu, x1, sl1);
        a[2] = __float_as_uint(odd ? t1 : t0);
        t0 = __shfl_sync(0xffffffffu, y0, sl1);
        t1 = __shfl_sync(0xffffffffu, y1, sl1);
        a[3] = __float_as_uint(odd ? t1 : t0);

        int kk = k7*8 + tig;
#pragma unroll
        for (int nt = 0; nt < 4; nt++) {
            unsigned b[2];
            b[0] = __float_as_uint(vsm[kk    ][nt*8 + gid]);
            b[1] = __float_as_uint(vsm[kk + 4][nt*8 + gid]);
            mma8(oacc[nt], a, b);
        }
    }

    float* op = g_ao + ((size_t)win * NTOK) * DIM + head * HD;
#pragma unroll
    for (int nt = 0; nt < 4; nt++) {
#pragma unroll
        for (int e = 0; e < 4; e++) {
            int i = (e >= 2) ? row_hi : row_lo;
            int d = nt*8 + tig*2 + (e & 1);
            if (i < NTOK) op[(size_t)i * DIM + d] = tfround(oacc[nt][e]);
        }
    }
}

// ---------------- launch ----------------
static float* sym_ptr(const void* sym) {
    void* p = nullptr;
    cudaGetSymbolAddress(&p, sym);
    return (float*)p;
}

extern "C" void kernel_launch(void* const* d_in, const int* in_sizes, int n_in,
                              void* d_out, int out_size) {
    const float* x       = (const float*)d_in[0];
    const float* n1g     = (const float*)d_in[1];
    const float* n1b     = (const float*)d_in[2];
    const float* qkv_w   = (const float*)d_in[3];
    const float* qkv_b   = (const float*)d_in[4];
    const float* proj_w  = (const float*)d_in[5];
    const float* proj_b  = (const float*)d_in[6];
    const float* btab    = (const float*)d_in[7];
    const float* n2g     = (const float*)d_in[8];
    const float* n2b     = (const float*)d_in[9];
    const float* fc1_w   = (const float*)d_in[10];
    const float* fc1_b   = (const float*)d_in[11];
    const float* fc2_w   = (const float*)d_in[12];
    const float* fc2_b   = (const float*)d_in[13];
    float* outp = (float*)d_out;

    float* hln = sym_ptr(g_hln);
    float* q   = sym_ptr(g_q);
    float* k   = sym_ptr(g_k);
    float* v   = sym_ptr(g_v);
    float* ao  = sym_ptr(g_ao);
    float* xn  = sym_ptr(g_xn);
    float* ml  = sym_ptr(g_ml);
    float* wr  = sym_ptr(g_wr);

    round_w<<<(W_TOTAL + 255)/256, 256>>>(qkv_w, proj_w, fc1_w, fc2_w);
    ln_kernel<1><<<TTOK/8, 256>>>(x, n1g, n1b, hln);
    gemm_tc<0><<<dim3((3*DIM)/64, TTOK/256), 256>>>(hln, wr + W_QKV_OFF, qkv_b, DIM, 3*DIM,
                                                    nullptr, q, k, v);
    attn_kernel<<<BW*HEADS, 128>>>(btab);
    gemm_tc<1><<<dim3(DIM/64, TTOK/256), 256>>>(ao, wr + W_PROJ_OFF, proj_b, DIM, DIM,
                                                x, xn, nullptr, nullptr);
    ln_kernel<0><<<TTOK/8, 256>>>(xn, n2g, n2b, hln);
    gemm_tc<2><<<dim3((4*DIM)/64, TTOK/256), 256>>>(hln, wr + W_FC1_OFF, fc1_b, DIM, 4*DIM,
                                                    nullptr, ml, nullptr, nullptr);
    gemm_tc<3><<<dim3(DIM/64, TTOK/256), 256>>>(ml, wr + W_FC2_OFF, fc2_b, 4*DIM, DIM,
                                                xn, outp, nullptr, nullptr);
}